// round 15
// baseline (speedup 1.0000x reference)
#include <cuda_runtime.h>
#include <cuda_fp16.h>
#include <cstdint>

// ---------------------------------------------------------------------------
// FlashMoERouter on GB300 (sm_103a) — HMMA mma.sync, fp16 2-way split.
// R15: R10 inner loop verbatim; ring slots carry TWO K-chunks (32 slots,
//      2-stage ring, 224KB smem) + WL trimmed to gate-only columns.
// ---------------------------------------------------------------------------

#define SW128(o) ((o) ^ (((o) >> 3) & 0x70))

static constexpr int NTOK   = 16384;
static constexpr int DIM    = 4096;
static constexpr int NOUT   = 128;
static constexpr int NEXP   = 64;
static constexpr int MT     = 128;
static constexpr int KC     = 64;           // K per chunk (per sub-tile)
static constexpr int NIT    = DIM / KC;     // 64 chunks
static constexpr int NSLOT  = NIT / 2;      // 32 ring slots (2 chunks each)
static constexpr int TILE_B = 128 * 128;    // 16KB (W hi)
static constexpr int TILE_L = 64 * 128;     // 8KB  (W lo, gate cols only)

// per-chunk sub-tile layout (identical to R10 except WL 8KB)
static constexpr int OFF_XH = 0;            // 16KB
static constexpr int OFF_XL = 16384;        // 16KB
static constexpr int OFF_WH = 32768;        // 16KB
static constexpr int OFF_WL = 49152;        // 8KB
static constexpr int SUB_B  = 57344;        // 56KB per chunk
static constexpr int BUF_B  = 2 * SUB_B;    // 112KB per slot
static constexpr int NSTAGE = 2;
static constexpr int OFF_BAR = NSTAGE * BUF_B;      // 229376
static constexpr int SMEM_SZ = OFF_BAR + 64;        // 229440
static constexpr int EPI_LO1 = 66048;               // lo1[128][65]
static constexpr int EPI_LO2 = 99328;               // lo2[128][65]

__device__ __align__(16) unsigned char g_wh[NIT * TILE_B];
__device__ __align__(16) unsigned char g_wl[NIT * TILE_L];

// ---------------- helpers ----------------
__device__ __forceinline__ uint32_t smem_u32(const void* p) {
    uint32_t a;
    asm("{ .reg .u64 t; cvta.to.shared.u64 t, %1; cvt.u32.u64 %0, t; }"
        : "=r"(a) : "l"(p));
    return a;
}
__device__ __forceinline__ void cp_async16(uint32_t s, const void* g) {
    asm volatile("cp.async.cg.shared.global [%0], [%1], 16;" :: "r"(s), "l"(g) : "memory");
}
#define CP_COMMIT() asm volatile("cp.async.commit_group;" ::: "memory")
#define CP_WAIT0()  asm volatile("cp.async.wait_group 0;" ::: "memory")

#define MBARRIER_INIT(addr, cnt) \
    asm volatile("mbarrier.init.shared.b64 [%0], %1;" :: "r"(addr), "r"(cnt) : "memory")
#define MBARRIER_ARRIVE(addr) \
    asm volatile("mbarrier.arrive.shared.b64 _, [%0];" :: "r"(addr) : "memory")
#define MBARRIER_WAIT_PARITY(addr, par) do {                                        \
    uint32_t _m = (addr), _p = (par), _d;                                           \
    asm volatile("{ .reg .pred p; mbarrier.try_wait.parity.acquire.cta.shared::cta.b64 p, [%1], %2; selp.b32 %0,1,0,p; }" \
                 : "=r"(_d) : "r"(_m), "r"(_p) : "memory");                         \
    if (!_d) {                                                                      \
        asm volatile("{ .reg .pred P;\n"                                            \
            "WL_%=: mbarrier.try_wait.parity.acquire.cta.shared::cta.b64 P, [%0], %1, 0x989680;\n" \
            "@P bra WD_%=;\n bra WL_%=;\n WD_%=: }"                                 \
            :: "r"(_m), "r"(_p) : "memory");                                        \
    }                                                                               \
} while (0)

__device__ __forceinline__ void ldsm4(uint32_t* r, uint32_t addr) {
    asm volatile("ldmatrix.sync.aligned.m8n8.x4.shared.b16 {%0,%1,%2,%3}, [%4];"
                 : "=r"(r[0]), "=r"(r[1]), "=r"(r[2]), "=r"(r[3]) : "r"(addr));
}
__device__ __forceinline__ void mma16816(float* d, const uint32_t* a,
                                         uint32_t b0, uint32_t b1) {
    asm volatile(
        "mma.sync.aligned.m16n8k16.row.col.f32.f16.f16.f32 "
        "{%0,%1,%2,%3}, {%4,%5,%6,%7}, {%8,%9}, {%0,%1,%2,%3};"
        : "+f"(d[0]), "+f"(d[1]), "+f"(d[2]), "+f"(d[3])
        : "r"(a[0]), "r"(a[1]), "r"(a[2]), "r"(a[3]), "r"(b0), "r"(b1));
}
__device__ __forceinline__ float wsum(float v) {
#pragma unroll
    for (int o = 16; o; o >>= 1) v += __shfl_xor_sync(0xffffffffu, v, o);
    return v;
}
__device__ __forceinline__ bool better(float v, int i, float w, int j) {
    return (v > w) || (v == w && i < j);
}

// ---------------- prep: split W into swizzled fp16 tiles ----------------
__global__ void prep_kernel(const float* __restrict__ gate_w,
                            const float* __restrict__ cap_w1) {
    int idx = blockIdx.x * blockDim.x + threadIdx.x;
    if (idx >= NOUT * DIM) return;
    int n = idx >> 12;
    int k = idx & (DIM - 1);
    float w = (n < NEXP) ? gate_w[n * DIM + k] : cap_w1[(n - NEXP) * DIM + k];
    __half wh = __float2half_rn(w);
    float res = (w - __half2float(wh)) * 2048.0f;
    __half wl = __float2half_rn(res);
    int t = k >> 6, kk = k & 63;
    int off = SW128(n * 128 + kk * 2);
    *(__half*)(g_wh + t * TILE_B + off) = wh;
    if (n < NEXP)
        *(__half*)(g_wl + t * TILE_L + off) = wl;
}

// ---------------- main kernel: 384 threads (8 consumers + 4 producers) -----
__global__ void __launch_bounds__(384, 1)
router_kernel(const float* __restrict__ x,
              const float* __restrict__ cap_b1, const float* __restrict__ ln_g,
              const float* __restrict__ ln_b,   const float* __restrict__ cap_w2,
              const float* __restrict__ cap_b2, const float* __restrict__ temp,
              const float* __restrict__ usage,  float* __restrict__ out) {
    extern __shared__ char smem[];
    const uint32_t sb = smem_u32(smem);
    const int tid  = threadIdx.x;
    const int wid  = tid >> 5;
    const int lane = tid & 31;
    const int tok0 = blockIdx.x * MT;

    const uint32_t bFull  = sb + OFF_BAR;         // full[s]  at +8*s
    const uint32_t bEmpty = sb + OFF_BAR + 32;    // empty[s] at +8*s

    if (tid == 0) {
#pragma unroll
        for (int s = 0; s < NSTAGE; s++) {
            MBARRIER_INIT(bFull + 8 * s, 128);    // producer threads
            MBARRIER_INIT(bEmpty + 8 * s, 256);   // consumer threads
        }
    }
    __syncthreads();

    if (wid >= 8) {
        // ================= PRODUCER (wid 8..11, 128 threads) ================
        const int pt = tid - 256;
        const int r0 = pt >> 2;
        const int kq = (pt & 3) * 16;
        const float* xrow0 = x + (size_t)(tok0 + r0) * DIM + kq;

        int pp = 1;
#pragma unroll 1
        for (int sl = 0; sl < NSLOT; sl++) {
            const int s = sl & 1;
            MBARRIER_WAIT_PARITY(bEmpty + 8 * s, pp);
            const uint32_t stg = sb + s * BUF_B;

            // both chunks' W tiles: per chunk WH 8 + WL 4 cp.async per thread
#pragma unroll
            for (int h = 0; h < 2; h++) {
                const int chunk = 2 * sl + h;
                const uint32_t sub = stg + h * SUB_B;
                const unsigned char* whs = g_wh + chunk * TILE_B;
                const unsigned char* wls = g_wl + chunk * TILE_L;
#pragma unroll
                for (int t = 0; t < 8; t++)
                    cp_async16(sub + OFF_WH + (pt + t * 128) * 16,
                               whs + (pt + t * 128) * 16);
#pragma unroll
                for (int t = 0; t < 4; t++)
                    cp_async16(sub + OFF_WL + (pt + t * 128) * 16,
                               wls + (pt + t * 128) * 16);
            }
            CP_COMMIT();

            // both chunks' x: 4 rows x 16 floats -> split -> swizzled STS
#pragma unroll
            for (int h = 0; h < 2; h++) {
                const int chunk = 2 * sl + h;
                char* dh = smem + s * BUF_B + h * SUB_B + OFF_XH;
                char* dl = smem + s * BUF_B + h * SUB_B + OFF_XL;
#pragma unroll
                for (int m = 0; m < 4; m++) {
                    const int row = r0 + m * 32;
                    const float4* px = (const float4*)(xrow0 + (size_t)(m * 32) * DIM
                                                       + (size_t)chunk * KC);
                    float4 f0 = px[0], f1 = px[1], f2 = px[2], f3 = px[3];
                    float fv[16];
                    *(float4*)(fv + 0)  = f0; *(float4*)(fv + 4)  = f1;
                    *(float4*)(fv + 8)  = f2; *(float4*)(fv + 12) = f3;
                    uint32_t hp[8], lp[8];
#pragma unroll
                    for (int q = 0; q < 8; q++) {
                        __half2 hh = __float22half2_rn(make_float2(fv[2*q], fv[2*q+1]));
                        float2 g = __half22float2(hh);
                        __half2 ll = __float22half2_rn(
                            make_float2((fv[2*q] - g.x) * 2048.0f,
                                        (fv[2*q+1] - g.y) * 2048.0f));
                        hp[q] = *(uint32_t*)&hh;
                        lp[q] = *(uint32_t*)&ll;
                    }
                    const uint32_t o0 = SW128((uint32_t)(row * 128 + kq * 2));
                    const uint32_t o1 = SW128((uint32_t)(row * 128 + kq * 2 + 16));
                    *(uint4*)(dh + o0) = make_uint4(hp[0], hp[1], hp[2], hp[3]);
                    *(uint4*)(dh + o1) = make_uint4(hp[4], hp[5], hp[6], hp[7]);
                    *(uint4*)(dl + o0) = make_uint4(lp[0], lp[1], lp[2], lp[3]);
                    *(uint4*)(dl + o1) = make_uint4(lp[4], lp[5], lp[6], lp[7]);
                }
            }

            CP_WAIT0();
            MBARRIER_ARRIVE(bFull + 8 * s);
            if (s == NSTAGE - 1) pp ^= 1;
        }
    } else {
        // ================= CONSUMER (wid 0..7): M64 x N64 each ==============
        // p = wid>>1: 0 = hi cols 0-63, 1 = hi cols 64-127,
        //             2 = loT1 (xh*wl, gate), 3 = loT2 (xl*wh, gate)
        const int mt      = wid & 1;
        const int p       = wid >> 1;
        const int rowbase = mt * 64;
        const int aOff    = (p == 3) ? OFF_XL : OFF_XH;
        const int bOff    = (p == 2) ? OFF_WL : OFF_WH;
        const int nbase   = (p == 1) ? 64 : 0;

        const int g  = lane >> 3;
        const int lr = lane & 7;
        const uint32_t rowA = (uint32_t)(rowbase + (g & 1) * 8 + lr) * 128;
        const uint32_t rowB = (uint32_t)(nbase   + (g & 1) * 8 + lr) * 128;
        const uint32_t kx   = (uint32_t)(((g >> 1) ^ lr) << 4);

        float acc[4][8][4];
#pragma unroll
        for (int a = 0; a < 4; a++)
#pragma unroll
            for (int b = 0; b < 8; b++)
#pragma unroll
                for (int c = 0; c < 4; c++) acc[a][b][c] = 0.0f;

        int pc = 0;
#pragma unroll 1
        for (int sl = 0; sl < NSLOT; sl++) {
            const int s = sl & 1;
            MBARRIER_WAIT_PARITY(bFull + 8 * s, pc);

#pragma unroll
            for (int h = 0; h < 2; h++) {
                const uint32_t sub = sb + s * BUF_B + h * SUB_B;
                const uint32_t aB = sub + aOff + rowA;
                const uint32_t bB = sub + bOff + rowB;
#pragma unroll
                for (int ks = 0; ks < 4; ks++) {
                    const uint32_t ko = ((uint32_t)(((ks + wid) & 3) * 32)) ^ kx;
                    uint32_t a[4][4], b[4][4];
#pragma unroll
                    for (int mi = 0; mi < 4; mi++) ldsm4(a[mi], aB + mi * 2048 + ko);
#pragma unroll
                    for (int nj = 0; nj < 4; nj++) ldsm4(b[nj], bB + nj * 2048 + ko);
#pragma unroll
                    for (int mi = 0; mi < 4; mi++)
#pragma unroll
                        for (int nj = 0; nj < 4; nj++) {
                            mma16816(acc[mi][2*nj],   a[mi], b[nj][0], b[nj][2]);
                            mma16816(acc[mi][2*nj+1], a[mi], b[nj][1], b[nj][3]);
                        }
                }
            }
            MBARRIER_ARRIVE(bEmpty + 8 * s);
            if (s == NSTAGE - 1) pc ^= 1;
        }

        // stash accs to smem
        __syncthreads();
        float* sc  = (float*)smem;                   // [128][129]
        float* lo1 = (float*)(smem + EPI_LO1);       // [128][65]
        float* lo2 = (float*)(smem + EPI_LO2);       // [128][65]
        {
            float* dst; int stride, colbase;
            if (p == 0)      { dst = sc;  stride = 129; colbase = 0;  }
            else if (p == 1) { dst = sc;  stride = 129; colbase = 64; }
            else if (p == 2) { dst = lo1; stride = 65;  colbase = 0;  }
            else             { dst = lo2; stride = 65;  colbase = 0;  }
            const int r4 = lane >> 2, c2 = (lane & 3) * 2;
#pragma unroll
            for (int mi = 0; mi < 4; mi++)
#pragma unroll
                for (int n8 = 0; n8 < 8; n8++) {
                    int row = rowbase + mi * 16 + r4;
                    int col = colbase + n8 * 8 + c2;
                    dst[row * stride + col]           = acc[mi][n8][0];
                    dst[row * stride + col + 1]       = acc[mi][n8][1];
                    dst[(row + 8) * stride + col]     = acc[mi][n8][2];
                    dst[(row + 8) * stride + col + 1] = acc[mi][n8][3];
                }
        }
    }
    if (wid >= 8) __syncthreads();    // producers join the pre-stash barrier
    __syncthreads();                  // stash complete

    // ---- epilogue: per-token routing (12 warps) ----
    float* sc  = (float*)smem;
    float* lo1 = (float*)(smem + EPI_LO1);
    float* lo2 = (float*)(smem + EPI_LO2);
    const float u_a = usage[lane], u_b = usage[lane + 32];
    const float utot = wsum(u_a + u_b);
    const float lbs  = 0.1f / (utot + 1e-6f);
    const float lbp_a = u_a * lbs, lbp_b = u_b * lbs;
    const float tclip = fmaxf(temp[0], 0.1f);
    const float cb1a = cap_b1[lane],  cb1b = cap_b1[lane + 32];
    const float ga   = ln_g[lane],    gb   = ln_g[lane + 32];
    const float ba   = ln_b[lane],    bb   = ln_b[lane + 32];
    const float w2a  = cap_w2[lane],  w2b  = cap_w2[lane + 32];
    const float b2   = cap_b2[0];
    const float INV2048 = 4.8828125e-4f;

#pragma unroll 1
    for (int j = 0; j < 11; j++) {
        const int tl = j * 12 + wid;
        if (tl >= MT) break;
        const float* srow  = sc  + tl * 129;
        const float* l1row = lo1 + tl * 65;
        const float* l2row = lo2 + tl * 65;
        const float s_a = srow[lane]      + (l1row[lane]      + l2row[lane])      * INV2048;
        const float s_b = srow[lane + 32] + (l1row[lane + 32] + l2row[lane + 32]) * INV2048;
        const float h_a = srow[64 + lane] + cb1a;
        const float h_b = srow[96 + lane] + cb1b;

        const float mu  = wsum(h_a + h_b) * (1.0f / 64.0f);
        const float msq = wsum(h_a * h_a + h_b * h_b) * (1.0f / 64.0f);
        const float rstd = rsqrtf(msq - mu * mu + 1e-5f);
        const float na = (h_a - mu) * rstd * ga + ba;
        const float nb = (h_b - mu) * rstd * gb + bb;
        const float ge_a = 0.5f * na * (1.0f + erff(na * 0.70710678118654752f));
        const float ge_b = 0.5f * nb * (1.0f + erff(nb * 0.70710678118654752f));
        const float z = wsum(ge_a * w2a + ge_b * w2b) + b2;
        const float cap = 1.0f / (1.0f + expf(-z));
        const float scale = cap * tclip;

        const float gta = (s_a - lbp_a) * scale;
        const float gtb = (s_b - lbp_b) * scale;

        float v1, v2; int i1, i2;
        if (better(gta, lane, gtb, lane + 32)) { v1 = gta; i1 = lane;      v2 = gtb; i2 = lane + 32; }
        else                                   { v1 = gtb; i1 = lane + 32; v2 = gta; i2 = lane; }
#pragma unroll
        for (int o = 16; o; o >>= 1) {
            float ov1 = __shfl_xor_sync(0xffffffffu, v1, o);
            int   oi1 = __shfl_xor_sync(0xffffffffu, i1, o);
            float ov2 = __shfl_xor_sync(0xffffffffu, v2, o);
            int   oi2 = __shfl_xor_sync(0xffffffffu, i2, o);
            if (better(ov1, oi1, v1, i1)) {
                float c2v; int c2i;
                if (better(v1, i1, ov2, oi2)) { c2v = v1; c2i = i1; }
                else                          { c2v = ov2; c2i = oi2; }
                v1 = ov1; i1 = oi1; v2 = c2v; i2 = c2i;
            } else if (better(ov1, oi1, v2, i2)) {
                v2 = ov1; i2 = oi1;
            }
        }
        const float inv = 1.0f / (v1 + v2 + 1e-6f);
        const size_t ob = (size_t)(tok0 + tl) * 64;
        out[ob + lane]      = (lane == i1)      ? v1 * inv : ((lane == i2)      ? v2 * inv : 0.0f);
        out[ob + lane + 32] = (lane + 32 == i1) ? v1 * inv : ((lane + 32 == i2) ? v2 * inv : 0.0f);
    }
}

// ---------------- launch ----------------
extern "C" void kernel_launch(void* const* d_in, const int* in_sizes, int n_in,
                              void* d_out, int out_size) {
    const float* x      = (const float*)d_in[0];
    const float* gate_w = (const float*)d_in[1];
    const float* cap_w1 = (const float*)d_in[2];
    const float* cap_b1 = (const float*)d_in[3];
    const float* ln_g   = (const float*)d_in[4];
    const float* ln_b   = (const float*)d_in[5];
    const float* cap_w2 = (const float*)d_in[6];
    const float* cap_b2 = (const float*)d_in[7];
    const float* temp   = (const float*)d_in[8];
    const float* usage  = (const float*)d_in[9];
    float* out = (float*)d_out;

    cudaFuncSetAttribute(router_kernel,
                         cudaFuncAttributeMaxDynamicSharedMemorySize, SMEM_SZ);

    prep_kernel<<<(NOUT * DIM) / 256, 256>>>(gate_w, cap_w1);
    router_kernel<<<NTOK / MT, 384, SMEM_SZ>>>(x, cap_b1, ln_g, ln_b, cap_w2,
                                               cap_b2, temp, usage, out);
}

// round 16
// speedup vs baseline: 1.1277x; 1.1277x over previous
#include <cuda_runtime.h>
#include <cuda_fp16.h>
#include <cstdint>

// ---------------------------------------------------------------------------
// FlashMoERouter on GB300 (sm_103a) — HMMA mma.sync, fp16 2-way split.
// R16: R10 verbatim (8 fat M64xN64 consumers + 4 producers, per-chunk ring
//      slots, volatile ldsm/mma) + WL trimmed to gate-only 8KB + 4-stage ring.
// ---------------------------------------------------------------------------

#define SW128(o) ((o) ^ (((o) >> 3) & 0x70))

static constexpr int NTOK   = 16384;
static constexpr int DIM    = 4096;
static constexpr int NOUT   = 128;
static constexpr int NEXP   = 64;
static constexpr int MT     = 128;
static constexpr int KC     = 64;
static constexpr int NIT    = DIM / KC;     // 64
static constexpr int TILE_B = 128 * 128;    // 16KB (W hi)
static constexpr int TILE_L = 64 * 128;     // 8KB  (W lo, gate cols only)

static constexpr int OFF_XH = 0;            // 16KB
static constexpr int OFF_XL = 16384;        // 16KB
static constexpr int OFF_WH = 32768;        // 16KB
static constexpr int OFF_WL = 49152;        // 8KB
static constexpr int BUF_B  = 57344;        // 56KB stage
static constexpr int NSTAGE = 4;
static constexpr int OFF_BAR = NSTAGE * BUF_B;      // 229376
static constexpr int SMEM_SZ = OFF_BAR + 64;        // 229440
static constexpr int EPI_LO1 = 66048;               // lo1[128][65]
static constexpr int EPI_LO2 = 99328;               // lo2[128][65]

__device__ __align__(16) unsigned char g_wh[NIT * TILE_B];
__device__ __align__(16) unsigned char g_wl[NIT * TILE_L];

// ---------------- helpers ----------------
__device__ __forceinline__ uint32_t smem_u32(const void* p) {
    uint32_t a;
    asm("{ .reg .u64 t; cvta.to.shared.u64 t, %1; cvt.u32.u64 %0, t; }"
        : "=r"(a) : "l"(p));
    return a;
}
__device__ __forceinline__ void cp_async16(uint32_t s, const void* g) {
    asm volatile("cp.async.cg.shared.global [%0], [%1], 16;" :: "r"(s), "l"(g) : "memory");
}
#define CP_COMMIT() asm volatile("cp.async.commit_group;" ::: "memory")
#define CP_WAIT0()  asm volatile("cp.async.wait_group 0;" ::: "memory")

#define MBARRIER_INIT(addr, cnt) \
    asm volatile("mbarrier.init.shared.b64 [%0], %1;" :: "r"(addr), "r"(cnt) : "memory")
#define MBARRIER_ARRIVE(addr) \
    asm volatile("mbarrier.arrive.shared.b64 _, [%0];" :: "r"(addr) : "memory")
#define MBARRIER_WAIT_PARITY(addr, par) do {                                        \
    uint32_t _m = (addr), _p = (par), _d;                                           \
    asm volatile("{ .reg .pred p; mbarrier.try_wait.parity.acquire.cta.shared::cta.b64 p, [%1], %2; selp.b32 %0,1,0,p; }" \
                 : "=r"(_d) : "r"(_m), "r"(_p) : "memory");                         \
    if (!_d) {                                                                      \
        asm volatile("{ .reg .pred P;\n"                                            \
            "WL_%=: mbarrier.try_wait.parity.acquire.cta.shared::cta.b64 P, [%0], %1, 0x989680;\n" \
            "@P bra WD_%=;\n bra WL_%=;\n WD_%=: }"                                 \
            :: "r"(_m), "r"(_p) : "memory");                                        \
    }                                                                               \
} while (0)

__device__ __forceinline__ void ldsm4(uint32_t* r, uint32_t addr) {
    asm volatile("ldmatrix.sync.aligned.m8n8.x4.shared.b16 {%0,%1,%2,%3}, [%4];"
                 : "=r"(r[0]), "=r"(r[1]), "=r"(r[2]), "=r"(r[3]) : "r"(addr));
}
__device__ __forceinline__ void mma16816(float* d, const uint32_t* a,
                                         uint32_t b0, uint32_t b1) {
    asm volatile(
        "mma.sync.aligned.m16n8k16.row.col.f32.f16.f16.f32 "
        "{%0,%1,%2,%3}, {%4,%5,%6,%7}, {%8,%9}, {%0,%1,%2,%3};"
        : "+f"(d[0]), "+f"(d[1]), "+f"(d[2]), "+f"(d[3])
        : "r"(a[0]), "r"(a[1]), "r"(a[2]), "r"(a[3]), "r"(b0), "r"(b1));
}
__device__ __forceinline__ float wsum(float v) {
#pragma unroll
    for (int o = 16; o; o >>= 1) v += __shfl_xor_sync(0xffffffffu, v, o);
    return v;
}
__device__ __forceinline__ bool better(float v, int i, float w, int j) {
    return (v > w) || (v == w && i < j);
}

// ---------------- prep: split W into swizzled fp16 tiles ----------------
__global__ void prep_kernel(const float* __restrict__ gate_w,
                            const float* __restrict__ cap_w1) {
    int idx = blockIdx.x * blockDim.x + threadIdx.x;
    if (idx >= NOUT * DIM) return;
    int n = idx >> 12;
    int k = idx & (DIM - 1);
    float w = (n < NEXP) ? gate_w[n * DIM + k] : cap_w1[(n - NEXP) * DIM + k];
    __half wh = __float2half_rn(w);
    float res = (w - __half2float(wh)) * 2048.0f;
    __half wl = __float2half_rn(res);
    int t = k >> 6, kk = k & 63;
    int off = SW128(n * 128 + kk * 2);
    *(__half*)(g_wh + t * TILE_B + off) = wh;
    if (n < NEXP)
        *(__half*)(g_wl + t * TILE_L + off) = wl;
}

// ---------------- main kernel: 384 threads (8 consumers + 4 producers) -----
__global__ void __launch_bounds__(384, 1)
router_kernel(const float* __restrict__ x,
              const float* __restrict__ cap_b1, const float* __restrict__ ln_g,
              const float* __restrict__ ln_b,   const float* __restrict__ cap_w2,
              const float* __restrict__ cap_b2, const float* __restrict__ temp,
              const float* __restrict__ usage,  float* __restrict__ out) {
    extern __shared__ char smem[];
    const uint32_t sb = smem_u32(smem);
    const int tid  = threadIdx.x;
    const int wid  = tid >> 5;
    const int lane = tid & 31;
    const int tok0 = blockIdx.x * MT;

    const uint32_t bFull  = sb + OFF_BAR;         // full[s]  at +8*s
    const uint32_t bEmpty = sb + OFF_BAR + 32;    // empty[s] at +8*s

    if (tid == 0) {
#pragma unroll
        for (int s = 0; s < NSTAGE; s++) {
            MBARRIER_INIT(bFull + 8 * s, 128);    // producer threads
            MBARRIER_INIT(bEmpty + 8 * s, 256);   // consumer threads
        }
    }
    __syncthreads();

    if (wid >= 8) {
        // ================= PRODUCER (wid 8..11, 128 threads) ================
        const int pt = tid - 256;
        const int r0 = pt >> 2;
        const int kq = (pt & 3) * 16;
        const float* xrow0 = x + (size_t)(tok0 + r0) * DIM + kq;

        int pp = 1;
#pragma unroll 1
        for (int i = 0; i < NIT; i++) {
            const int s = i % NSTAGE;
            MBARRIER_WAIT_PARITY(bEmpty + 8 * s, pp);
            const uint32_t stg = sb + s * BUF_B;

            // W tiles: WH 8 + WL 4 cp.async per thread
            {
                const unsigned char* whs = g_wh + i * TILE_B;
                const unsigned char* wls = g_wl + i * TILE_L;
#pragma unroll
                for (int t = 0; t < 8; t++)
                    cp_async16(stg + OFF_WH + (pt + t * 128) * 16,
                               whs + (pt + t * 128) * 16);
#pragma unroll
                for (int t = 0; t < 4; t++)
                    cp_async16(stg + OFF_WL + (pt + t * 128) * 16,
                               wls + (pt + t * 128) * 16);
                CP_COMMIT();
            }

            // x: 4 rows x 16 floats -> split -> swizzled STS
#pragma unroll
            for (int m = 0; m < 4; m++) {
                const int row = r0 + m * 32;
                const float4* px = (const float4*)(xrow0 + (size_t)(m * 32) * DIM
                                                   + (size_t)i * KC);
                float4 f0 = px[0], f1 = px[1], f2 = px[2], f3 = px[3];
                float fv[16];
                *(float4*)(fv + 0)  = f0; *(float4*)(fv + 4)  = f1;
                *(float4*)(fv + 8)  = f2; *(float4*)(fv + 12) = f3;
                uint32_t hp[8], lp[8];
#pragma unroll
                for (int q = 0; q < 8; q++) {
                    __half2 h = __float22half2_rn(make_float2(fv[2*q], fv[2*q+1]));
                    float2 g = __half22float2(h);
                    __half2 l = __float22half2_rn(
                        make_float2((fv[2*q] - g.x) * 2048.0f,
                                    (fv[2*q+1] - g.y) * 2048.0f));
                    hp[q] = *(uint32_t*)&h;
                    lp[q] = *(uint32_t*)&l;
                }
                const uint32_t o0 = SW128((uint32_t)(row * 128 + kq * 2));
                const uint32_t o1 = SW128((uint32_t)(row * 128 + kq * 2 + 16));
                char* dh = smem + s * BUF_B + OFF_XH;
                char* dl = smem + s * BUF_B + OFF_XL;
                *(uint4*)(dh + o0) = make_uint4(hp[0], hp[1], hp[2], hp[3]);
                *(uint4*)(dh + o1) = make_uint4(hp[4], hp[5], hp[6], hp[7]);
                *(uint4*)(dl + o0) = make_uint4(lp[0], lp[1], lp[2], lp[3]);
                *(uint4*)(dl + o1) = make_uint4(lp[4], lp[5], lp[6], lp[7]);
            }

            CP_WAIT0();
            MBARRIER_ARRIVE(bFull + 8 * s);
            if (s == NSTAGE - 1) pp ^= 1;
        }
    } else {
        // ================= CONSUMER (wid 0..7): M64 x N64 each ==============
        // p = wid>>1: 0 = hi cols 0-63 (xh*wh), 1 = hi cols 64-127 (xh*wh),
        //             2 = loT1 (xh*wl, cols 0-63), 3 = loT2 (xl*wh, cols 0-63)
        const int mt      = wid & 1;
        const int p       = wid >> 1;
        const int rowbase = mt * 64;
        const int aOff    = (p == 3) ? OFF_XL : OFF_XH;
        const int bOff    = (p == 2) ? OFF_WL : OFF_WH;
        const int nbase   = (p == 1) ? 64 : 0;

        const int g  = lane >> 3;
        const int lr = lane & 7;
        const uint32_t rowA = (uint32_t)(rowbase + (g & 1) * 8 + lr) * 128;
        const uint32_t rowB = (uint32_t)(nbase   + (g & 1) * 8 + lr) * 128;
        const uint32_t kx   = (uint32_t)(((g >> 1) ^ lr) << 4);

        float acc[4][8][4];
#pragma unroll
        for (int a = 0; a < 4; a++)
#pragma unroll
            for (int b = 0; b < 8; b++)
#pragma unroll
                for (int c = 0; c < 4; c++) acc[a][b][c] = 0.0f;

        int pc = 0;
#pragma unroll 1
        for (int i = 0; i < NIT; i++) {
            const int s = i % NSTAGE;
            MBARRIER_WAIT_PARITY(bFull + 8 * s, pc);
            const uint32_t aB = sb + s * BUF_B + aOff + rowA;
            const uint32_t bB = sb + s * BUF_B + bOff + rowB;

#pragma unroll
            for (int ks = 0; ks < 4; ks++) {
                const uint32_t ko = ((uint32_t)(((ks + wid) & 3) * 32)) ^ kx;
                uint32_t a[4][4], b[4][4];
#pragma unroll
                for (int mi = 0; mi < 4; mi++) ldsm4(a[mi], aB + mi * 2048 + ko);
#pragma unroll
                for (int nj = 0; nj < 4; nj++) ldsm4(b[nj], bB + nj * 2048 + ko);
#pragma unroll
                for (int mi = 0; mi < 4; mi++)
#pragma unroll
                    for (int nj = 0; nj < 4; nj++) {
                        mma16816(acc[mi][2*nj],   a[mi], b[nj][0], b[nj][2]);
                        mma16816(acc[mi][2*nj+1], a[mi], b[nj][1], b[nj][3]);
                    }
            }
            MBARRIER_ARRIVE(bEmpty + 8 * s);
            if (s == NSTAGE - 1) pc ^= 1;
        }

        // stash accs to smem
        __syncthreads();
        float* sc  = (float*)smem;                   // [128][129]
        float* lo1 = (float*)(smem + EPI_LO1);       // [128][65]
        float* lo2 = (float*)(smem + EPI_LO2);       // [128][65]
        {
            float* dst; int stride, colbase;
            if (p == 0)      { dst = sc;  stride = 129; colbase = 0;  }
            else if (p == 1) { dst = sc;  stride = 129; colbase = 64; }
            else if (p == 2) { dst = lo1; stride = 65;  colbase = 0;  }
            else             { dst = lo2; stride = 65;  colbase = 0;  }
            const int r4 = lane >> 2, c2 = (lane & 3) * 2;
#pragma unroll
            for (int mi = 0; mi < 4; mi++)
#pragma unroll
                for (int n8 = 0; n8 < 8; n8++) {
                    int row = rowbase + mi * 16 + r4;
                    int col = colbase + n8 * 8 + c2;
                    dst[row * stride + col]           = acc[mi][n8][0];
                    dst[row * stride + col + 1]       = acc[mi][n8][1];
                    dst[(row + 8) * stride + col]     = acc[mi][n8][2];
                    dst[(row + 8) * stride + col + 1] = acc[mi][n8][3];
                }
        }
    }
    if (wid >= 8) __syncthreads();    // producers join the pre-stash barrier
    __syncthreads();                  // stash complete

    // ---- epilogue: per-token routing (12 warps) ----
    float* sc  = (float*)smem;
    float* lo1 = (float*)(smem + EPI_LO1);
    float* lo2 = (float*)(smem + EPI_LO2);
    const float u_a = usage[lane], u_b = usage[lane + 32];
    const float utot = wsum(u_a + u_b);
    const float lbs  = 0.1f / (utot + 1e-6f);
    const float lbp_a = u_a * lbs, lbp_b = u_b * lbs;
    const float tclip = fmaxf(temp[0], 0.1f);
    const float cb1a = cap_b1[lane],  cb1b = cap_b1[lane + 32];
    const float ga   = ln_g[lane],    gb   = ln_g[lane + 32];
    const float ba   = ln_b[lane],    bb   = ln_b[lane + 32];
    const float w2a  = cap_w2[lane],  w2b  = cap_w2[lane + 32];
    const float b2   = cap_b2[0];
    const float INV2048 = 4.8828125e-4f;

#pragma unroll 1
    for (int j = 0; j < 11; j++) {
        const int tl = j * 12 + wid;
        if (tl >= MT) break;
        const float* srow  = sc  + tl * 129;
        const float* l1row = lo1 + tl * 65;
        const float* l2row = lo2 + tl * 65;
        const float s_a = srow[lane]      + (l1row[lane]      + l2row[lane])      * INV2048;
        const float s_b = srow[lane + 32] + (l1row[lane + 32] + l2row[lane + 32]) * INV2048;
        const float h_a = srow[64 + lane] + cb1a;
        const float h_b = srow[96 + lane] + cb1b;

        const float mu  = wsum(h_a + h_b) * (1.0f / 64.0f);
        const float msq = wsum(h_a * h_a + h_b * h_b) * (1.0f / 64.0f);
        const float rstd = rsqrtf(msq - mu * mu + 1e-5f);
        const float na = (h_a - mu) * rstd * ga + ba;
        const float nb = (h_b - mu) * rstd * gb + bb;
        const float ge_a = 0.5f * na * (1.0f + erff(na * 0.70710678118654752f));
        const float ge_b = 0.5f * nb * (1.0f + erff(nb * 0.70710678118654752f));
        const float z = wsum(ge_a * w2a + ge_b * w2b) + b2;
        const float cap = 1.0f / (1.0f + expf(-z));
        const float scale = cap * tclip;

        const float gta = (s_a - lbp_a) * scale;
        const float gtb = (s_b - lbp_b) * scale;

        float v1, v2; int i1, i2;
        if (better(gta, lane, gtb, lane + 32)) { v1 = gta; i1 = lane;      v2 = gtb; i2 = lane + 32; }
        else                                   { v1 = gtb; i1 = lane + 32; v2 = gta; i2 = lane; }
#pragma unroll
        for (int o = 16; o; o >>= 1) {
            float ov1 = __shfl_xor_sync(0xffffffffu, v1, o);
            int   oi1 = __shfl_xor_sync(0xffffffffu, i1, o);
            float ov2 = __shfl_xor_sync(0xffffffffu, v2, o);
            int   oi2 = __shfl_xor_sync(0xffffffffu, i2, o);
            if (better(ov1, oi1, v1, i1)) {
                float c2v; int c2i;
                if (better(v1, i1, ov2, oi2)) { c2v = v1; c2i = i1; }
                else                          { c2v = ov2; c2i = oi2; }
                v1 = ov1; i1 = oi1; v2 = c2v; i2 = c2i;
            } else if (better(ov1, oi1, v2, i2)) {
                v2 = ov1; i2 = oi1;
            }
        }
        const float inv = 1.0f / (v1 + v2 + 1e-6f);
        const size_t ob = (size_t)(tok0 + tl) * 64;
        out[ob + lane]      = (lane == i1)      ? v1 * inv : ((lane == i2)      ? v2 * inv : 0.0f);
        out[ob + lane + 32] = (lane + 32 == i1) ? v1 * inv : ((lane + 32 == i2) ? v2 * inv : 0.0f);
    }
}

// ---------------- launch ----------------
extern "C" void kernel_launch(void* const* d_in, const int* in_sizes, int n_in,
                              void* d_out, int out_size) {
    const float* x      = (const float*)d_in[0];
    const float* gate_w = (const float*)d_in[1];
    const float* cap_w1 = (const float*)d_in[2];
    const float* cap_b1 = (const float*)d_in[3];
    const float* ln_g   = (const float*)d_in[4];
    const float* ln_b   = (const float*)d_in[5];
    const float* cap_w2 = (const float*)d_in[6];
    const float* cap_b2 = (const float*)d_in[7];
    const float* temp   = (const float*)d_in[8];
    const float* usage  = (const float*)d_in[9];
    float* out = (float*)d_out;

    cudaFuncSetAttribute(router_kernel,
                         cudaFuncAttributeMaxDynamicSharedMemorySize, SMEM_SZ);

    prep_kernel<<<(NOUT * DIM) / 256, 256>>>(gate_w, cap_w1);
    router_kernel<<<NTOK / MT, 384, SMEM_SZ>>>(x, cap_b1, ln_g, ln_b, cap_w2,
                                               cap_b2, temp, usage, out);
}

// round 17
// speedup vs baseline: 1.3677x; 1.2128x over previous
#include <cuda_runtime.h>
#include <cuda_fp16.h>
#include <cstdint>

// ---------------------------------------------------------------------------
// FlashMoERouter on GB300 (sm_103a) — HMMA mma.sync, fp16 2-way split.
// R17: R10 byte-for-byte + ONE change: WL trimmed to gate-only columns
//      (stage 64KB -> 56KB, smem 196KB -> 172KB, 12.5% fewer W-fill bytes,
//      L1D carveout 32KB -> 56KB).
// ---------------------------------------------------------------------------

#define SW128(o) ((o) ^ (((o) >> 3) & 0x70))

static constexpr int NTOK   = 16384;
static constexpr int DIM    = 4096;
static constexpr int NOUT   = 128;
static constexpr int NEXP   = 64;
static constexpr int MT     = 128;
static constexpr int KC     = 64;
static constexpr int NIT    = DIM / KC;     // 64
static constexpr int TILE_B = 128 * 128;    // 16KB (W hi)
static constexpr int TILE_L = 64 * 128;     // 8KB  (W lo, gate cols only)

static constexpr int OFF_XH = 0;            // 16KB
static constexpr int OFF_XL = 16384;        // 16KB
static constexpr int OFF_WH = 32768;        // 16KB
static constexpr int OFF_WL = 49152;        // 8KB
static constexpr int BUF_B  = 57344;        // 56KB stage
static constexpr int NSTAGE = 3;
static constexpr int OFF_BAR = NSTAGE * BUF_B;      // 172032
static constexpr int SMEM_SZ = OFF_BAR + 64;        // 172096
static constexpr int EPI_LO1 = 66048;               // lo1[128][65]
static constexpr int EPI_LO2 = 99328;               // lo2[128][65]

__device__ __align__(16) unsigned char g_wh[NIT * TILE_B];
__device__ __align__(16) unsigned char g_wl[NIT * TILE_L];

// ---------------- helpers ----------------
__device__ __forceinline__ uint32_t smem_u32(const void* p) {
    uint32_t a;
    asm("{ .reg .u64 t; cvta.to.shared.u64 t, %1; cvt.u32.u64 %0, t; }"
        : "=r"(a) : "l"(p));
    return a;
}
__device__ __forceinline__ void cp_async16(uint32_t s, const void* g) {
    asm volatile("cp.async.cg.shared.global [%0], [%1], 16;" :: "r"(s), "l"(g) : "memory");
}
#define CP_COMMIT() asm volatile("cp.async.commit_group;" ::: "memory")
#define CP_WAIT0()  asm volatile("cp.async.wait_group 0;" ::: "memory")

#define MBARRIER_INIT(addr, cnt) \
    asm volatile("mbarrier.init.shared.b64 [%0], %1;" :: "r"(addr), "r"(cnt) : "memory")
#define MBARRIER_ARRIVE(addr) \
    asm volatile("mbarrier.arrive.shared.b64 _, [%0];" :: "r"(addr) : "memory")
#define MBARRIER_WAIT_PARITY(addr, par) do {                                        \
    uint32_t _m = (addr), _p = (par), _d;                                           \
    asm volatile("{ .reg .pred p; mbarrier.try_wait.parity.acquire.cta.shared::cta.b64 p, [%1], %2; selp.b32 %0,1,0,p; }" \
                 : "=r"(_d) : "r"(_m), "r"(_p) : "memory");                         \
    if (!_d) {                                                                      \
        asm volatile("{ .reg .pred P;\n"                                            \
            "WL_%=: mbarrier.try_wait.parity.acquire.cta.shared::cta.b64 P, [%0], %1, 0x989680;\n" \
            "@P bra WD_%=;\n bra WL_%=;\n WD_%=: }"                                 \
            :: "r"(_m), "r"(_p) : "memory");                                        \
    }                                                                               \
} while (0)

__device__ __forceinline__ void ldsm4(uint32_t* r, uint32_t addr) {
    asm volatile("ldmatrix.sync.aligned.m8n8.x4.shared.b16 {%0,%1,%2,%3}, [%4];"
                 : "=r"(r[0]), "=r"(r[1]), "=r"(r[2]), "=r"(r[3]) : "r"(addr));
}
__device__ __forceinline__ void mma16816(float* d, const uint32_t* a,
                                         uint32_t b0, uint32_t b1) {
    asm volatile(
        "mma.sync.aligned.m16n8k16.row.col.f32.f16.f16.f32 "
        "{%0,%1,%2,%3}, {%4,%5,%6,%7}, {%8,%9}, {%0,%1,%2,%3};"
        : "+f"(d[0]), "+f"(d[1]), "+f"(d[2]), "+f"(d[3])
        : "r"(a[0]), "r"(a[1]), "r"(a[2]), "r"(a[3]), "r"(b0), "r"(b1));
}
__device__ __forceinline__ float wsum(float v) {
#pragma unroll
    for (int o = 16; o; o >>= 1) v += __shfl_xor_sync(0xffffffffu, v, o);
    return v;
}
__device__ __forceinline__ bool better(float v, int i, float w, int j) {
    return (v > w) || (v == w && i < j);
}

// ---------------- prep: split W into swizzled fp16 tiles ----------------
__global__ void prep_kernel(const float* __restrict__ gate_w,
                            const float* __restrict__ cap_w1) {
    int idx = blockIdx.x * blockDim.x + threadIdx.x;
    if (idx >= NOUT * DIM) return;
    int n = idx >> 12;
    int k = idx & (DIM - 1);
    float w = (n < NEXP) ? gate_w[n * DIM + k] : cap_w1[(n - NEXP) * DIM + k];
    __half wh = __float2half_rn(w);
    float res = (w - __half2float(wh)) * 2048.0f;
    __half wl = __float2half_rn(res);
    int t = k >> 6, kk = k & 63;
    int off = SW128(n * 128 + kk * 2);
    *(__half*)(g_wh + t * TILE_B + off) = wh;
    if (n < NEXP)
        *(__half*)(g_wl + t * TILE_L + off) = wl;
}

// ---------------- main kernel: 384 threads (8 consumers + 4 producers) -----
__global__ void __launch_bounds__(384, 1)
router_kernel(const float* __restrict__ x,
              const float* __restrict__ cap_b1, const float* __restrict__ ln_g,
              const float* __restrict__ ln_b,   const float* __restrict__ cap_w2,
              const float* __restrict__ cap_b2, const float* __restrict__ temp,
              const float* __restrict__ usage,  float* __restrict__ out) {
    extern __shared__ char smem[];
    const uint32_t sb = smem_u32(smem);
    const int tid  = threadIdx.x;
    const int wid  = tid >> 5;
    const int lane = tid & 31;
    const int tok0 = blockIdx.x * MT;

    const uint32_t bFull  = sb + OFF_BAR;         // full[s]  at +8*s
    const uint32_t bEmpty = sb + OFF_BAR + 32;    // empty[s] at +8*s

    if (tid == 0) {
#pragma unroll
        for (int s = 0; s < NSTAGE; s++) {
            MBARRIER_INIT(bFull + 8 * s, 128);    // producer threads
            MBARRIER_INIT(bEmpty + 8 * s, 256);   // consumer threads
        }
    }
    __syncthreads();

    if (wid >= 8) {
        // ================= PRODUCER (wid 8..11, 128 threads) ================
        const int pt = tid - 256;
        const int r0 = pt >> 2;
        const int kq = (pt & 3) * 16;
        const float* xrow0 = x + (size_t)(tok0 + r0) * DIM + kq;

        int pp = 1;
#pragma unroll 1
        for (int i = 0; i < NIT; i++) {
            const int s = i % NSTAGE;
            MBARRIER_WAIT_PARITY(bEmpty + 8 * s, pp);
            const uint32_t stg = sb + s * BUF_B;

            // W tiles: WH 8 + WL 4 cp.async per thread
            {
                const unsigned char* whs = g_wh + i * TILE_B;
                const unsigned char* wls = g_wl + i * TILE_L;
#pragma unroll
                for (int t = 0; t < 8; t++)
                    cp_async16(stg + OFF_WH + (pt + t * 128) * 16,
                               whs + (pt + t * 128) * 16);
#pragma unroll
                for (int t = 0; t < 4; t++)
                    cp_async16(stg + OFF_WL + (pt + t * 128) * 16,
                               wls + (pt + t * 128) * 16);
                CP_COMMIT();
            }

            // x: 4 rows x 16 floats -> split -> swizzled STS
#pragma unroll
            for (int m = 0; m < 4; m++) {
                const int row = r0 + m * 32;
                const float4* px = (const float4*)(xrow0 + (size_t)(m * 32) * DIM
                                                   + (size_t)i * KC);
                float4 f0 = px[0], f1 = px[1], f2 = px[2], f3 = px[3];
                float fv[16];
                *(float4*)(fv + 0)  = f0; *(float4*)(fv + 4)  = f1;
                *(float4*)(fv + 8)  = f2; *(float4*)(fv + 12) = f3;
                uint32_t hp[8], lp[8];
#pragma unroll
                for (int q = 0; q < 8; q++) {
                    __half2 h = __float22half2_rn(make_float2(fv[2*q], fv[2*q+1]));
                    float2 g = __half22float2(h);
                    __half2 l = __float22half2_rn(
                        make_float2((fv[2*q] - g.x) * 2048.0f,
                                    (fv[2*q+1] - g.y) * 2048.0f));
                    hp[q] = *(uint32_t*)&h;
                    lp[q] = *(uint32_t*)&l;
                }
                const uint32_t o0 = SW128((uint32_t)(row * 128 + kq * 2));
                const uint32_t o1 = SW128((uint32_t)(row * 128 + kq * 2 + 16));
                char* dh = smem + s * BUF_B + OFF_XH;
                char* dl = smem + s * BUF_B + OFF_XL;
                *(uint4*)(dh + o0) = make_uint4(hp[0], hp[1], hp[2], hp[3]);
                *(uint4*)(dh + o1) = make_uint4(hp[4], hp[5], hp[6], hp[7]);
                *(uint4*)(dl + o0) = make_uint4(lp[0], lp[1], lp[2], lp[3]);
                *(uint4*)(dl + o1) = make_uint4(lp[4], lp[5], lp[6], lp[7]);
            }

            CP_WAIT0();
            MBARRIER_ARRIVE(bFull + 8 * s);
            if (s == NSTAGE - 1) pp ^= 1;
        }
    } else {
        // ================= CONSUMER (wid 0..7): M64 x N64 each ==============
        // p = wid>>1: 0 = hi cols 0-63 (xh*wh), 1 = hi cols 64-127 (xh*wh),
        //             2 = loT1 (xh*wl, cols 0-63), 3 = loT2 (xl*wh, cols 0-63)
        const int mt      = wid & 1;
        const int p       = wid >> 1;
        const int rowbase = mt * 64;
        const int aOff    = (p == 3) ? OFF_XL : OFF_XH;
        const int bOff    = (p == 2) ? OFF_WL : OFF_WH;
        const int nbase   = (p == 1) ? 64 : 0;

        const int g  = lane >> 3;
        const int lr = lane & 7;
        const uint32_t rowA = (uint32_t)(rowbase + (g & 1) * 8 + lr) * 128;
        const uint32_t rowB = (uint32_t)(nbase   + (g & 1) * 8 + lr) * 128;
        const uint32_t kx   = (uint32_t)(((g >> 1) ^ lr) << 4);

        float acc[4][8][4];
#pragma unroll
        for (int a = 0; a < 4; a++)
#pragma unroll
            for (int b = 0; b < 8; b++)
#pragma unroll
                for (int c = 0; c < 4; c++) acc[a][b][c] = 0.0f;

        int pc = 0;
#pragma unroll 1
        for (int i = 0; i < NIT; i++) {
            const int s = i % NSTAGE;
            MBARRIER_WAIT_PARITY(bFull + 8 * s, pc);
            const uint32_t aB = sb + s * BUF_B + aOff + rowA;
            const uint32_t bB = sb + s * BUF_B + bOff + rowB;

#pragma unroll
            for (int ks = 0; ks < 4; ks++) {
                const uint32_t ko = ((uint32_t)(((ks + wid) & 3) * 32)) ^ kx;
                uint32_t a[4][4], b[4][4];
#pragma unroll
                for (int mi = 0; mi < 4; mi++) ldsm4(a[mi], aB + mi * 2048 + ko);
#pragma unroll
                for (int nj = 0; nj < 4; nj++) ldsm4(b[nj], bB + nj * 2048 + ko);
#pragma unroll
                for (int mi = 0; mi < 4; mi++)
#pragma unroll
                    for (int nj = 0; nj < 4; nj++) {
                        mma16816(acc[mi][2*nj],   a[mi], b[nj][0], b[nj][2]);
                        mma16816(acc[mi][2*nj+1], a[mi], b[nj][1], b[nj][3]);
                    }
            }
            MBARRIER_ARRIVE(bEmpty + 8 * s);
            if (s == NSTAGE - 1) pc ^= 1;
        }

        // stash accs to smem
        __syncthreads();
        float* sc  = (float*)smem;                   // [128][129]
        float* lo1 = (float*)(smem + EPI_LO1);       // [128][65]
        float* lo2 = (float*)(smem + EPI_LO2);       // [128][65]
        {
            float* dst; int stride, colbase;
            if (p == 0)      { dst = sc;  stride = 129; colbase = 0;  }
            else if (p == 1) { dst = sc;  stride = 129; colbase = 64; }
            else if (p == 2) { dst = lo1; stride = 65;  colbase = 0;  }
            else             { dst = lo2; stride = 65;  colbase = 0;  }
            const int r4 = lane >> 2, c2 = (lane & 3) * 2;
#pragma unroll
            for (int mi = 0; mi < 4; mi++)
#pragma unroll
                for (int n8 = 0; n8 < 8; n8++) {
                    int row = rowbase + mi * 16 + r4;
                    int col = colbase + n8 * 8 + c2;
                    dst[row * stride + col]           = acc[mi][n8][0];
                    dst[row * stride + col + 1]       = acc[mi][n8][1];
                    dst[(row + 8) * stride + col]     = acc[mi][n8][2];
                    dst[(row + 8) * stride + col + 1] = acc[mi][n8][3];
                }
        }
    }
    if (wid >= 8) __syncthreads();    // producers join the pre-stash barrier
    __syncthreads();                  // stash complete

    // ---- epilogue: per-token routing (12 warps) ----
    float* sc  = (float*)smem;
    float* lo1 = (float*)(smem + EPI_LO1);
    float* lo2 = (float*)(smem + EPI_LO2);
    const float u_a = usage[lane], u_b = usage[lane + 32];
    const float utot = wsum(u_a + u_b);
    const float lbs  = 0.1f / (utot + 1e-6f);
    const float lbp_a = u_a * lbs, lbp_b = u_b * lbs;
    const float tclip = fmaxf(temp[0], 0.1f);
    const float cb1a = cap_b1[lane],  cb1b = cap_b1[lane + 32];
    const float ga   = ln_g[lane],    gb   = ln_g[lane + 32];
    const float ba   = ln_b[lane],    bb   = ln_b[lane + 32];
    const float w2a  = cap_w2[lane],  w2b  = cap_w2[lane + 32];
    const float b2   = cap_b2[0];
    const float INV2048 = 4.8828125e-4f;

#pragma unroll 1
    for (int j = 0; j < 11; j++) {
        const int tl = j * 12 + wid;
        if (tl >= MT) break;
        const float* srow  = sc  + tl * 129;
        const float* l1row = lo1 + tl * 65;
        const float* l2row = lo2 + tl * 65;
        const float s_a = srow[lane]      + (l1row[lane]      + l2row[lane])      * INV2048;
        const float s_b = srow[lane + 32] + (l1row[lane + 32] + l2row[lane + 32]) * INV2048;
        const float h_a = srow[64 + lane] + cb1a;
        const float h_b = srow[96 + lane] + cb1b;

        const float mu  = wsum(h_a + h_b) * (1.0f / 64.0f);
        const float msq = wsum(h_a * h_a + h_b * h_b) * (1.0f / 64.0f);
        const float rstd = rsqrtf(msq - mu * mu + 1e-5f);
        const float na = (h_a - mu) * rstd * ga + ba;
        const float nb = (h_b - mu) * rstd * gb + bb;
        const float ge_a = 0.5f * na * (1.0f + erff(na * 0.70710678118654752f));
        const float ge_b = 0.5f * nb * (1.0f + erff(nb * 0.70710678118654752f));
        const float z = wsum(ge_a * w2a + ge_b * w2b) + b2;
        const float cap = 1.0f / (1.0f + expf(-z));
        const float scale = cap * tclip;

        const float gta = (s_a - lbp_a) * scale;
        const float gtb = (s_b - lbp_b) * scale;

        float v1, v2; int i1, i2;
        if (better(gta, lane, gtb, lane + 32)) { v1 = gta; i1 = lane;      v2 = gtb; i2 = lane + 32; }
        else                                   { v1 = gtb; i1 = lane + 32; v2 = gta; i2 = lane; }
#pragma unroll
        for (int o = 16; o; o >>= 1) {
            float ov1 = __shfl_xor_sync(0xffffffffu, v1, o);
            int   oi1 = __shfl_xor_sync(0xffffffffu, i1, o);
            float ov2 = __shfl_xor_sync(0xffffffffu, v2, o);
            int   oi2 = __shfl_xor_sync(0xffffffffu, i2, o);
            if (better(ov1, oi1, v1, i1)) {
                float c2v; int c2i;
                if (better(v1, i1, ov2, oi2)) { c2v = v1; c2i = i1; }
                else                          { c2v = ov2; c2i = oi2; }
                v1 = ov1; i1 = oi1; v2 = c2v; i2 = c2i;
            } else if (better(ov1, oi1, v2, i2)) {
                v2 = ov1; i2 = oi1;
            }
        }
        const float inv = 1.0f / (v1 + v2 + 1e-6f);
        const size_t ob = (size_t)(tok0 + tl) * 64;
        out[ob + lane]      = (lane == i1)      ? v1 * inv : ((lane == i2)      ? v2 * inv : 0.0f);
        out[ob + lane + 32] = (lane + 32 == i1) ? v1 * inv : ((lane + 32 == i2) ? v2 * inv : 0.0f);
    }
}

// ---------------- launch ----------------
extern "C" void kernel_launch(void* const* d_in, const int* in_sizes, int n_in,
                              void* d_out, int out_size) {
    const float* x      = (const float*)d_in[0];
    const float* gate_w = (const float*)d_in[1];
    const float* cap_w1 = (const float*)d_in[2];
    const float* cap_b1 = (const float*)d_in[3];
    const float* ln_g   = (const float*)d_in[4];
    const float* ln_b   = (const float*)d_in[5];
    const float* cap_w2 = (const float*)d_in[6];
    const float* cap_b2 = (const float*)d_in[7];
    const float* temp   = (const float*)d_in[8];
    const float* usage  = (const float*)d_in[9];
    float* out = (float*)d_out;

    cudaFuncSetAttribute(router_kernel,
                         cudaFuncAttributeMaxDynamicSharedMemorySize, SMEM_SZ);

    prep_kernel<<<(NOUT * DIM) / 256, 256>>>(gate_w, cap_w1);
    router_kernel<<<NTOK / MT, 384, SMEM_SZ>>>(x, cap_b1, ln_g, ln_b, cap_w2,
                                               cap_b2, temp, usage, out);
}